// round 2
// baseline (speedup 1.0000x reference)
#include <cuda_runtime.h>
#include <cuda_bf16.h>
#include <cstdint>

// ---------------------------------------------------------------------------
// MetricLoss: x [1024, 64, 768] fp32 -> (loss_homo_scaled, loss_heter_scaled)
//   f = x.reshape(1024, 49152)
//   dist[j,k] = max(||f_j||^2 + ||f_k||^2 - 2 f_j.f_k, 0)
//   homo  = sum over unordered same-group pairs of dist        (groups of 8)
//   heter = sum over ORDERED diff-group pairs of max(1-dist,0)
//   out0 = 2*homo / (N*(bk-1)),  out1 = 2*heter / (N*(n_groups-1))
// Strategy: bf16 Gram (lower triangle only, split-K=4), cp.async double-
// buffered mma.sync mainloop, fp32 accum, deterministic tile reductions.
// ---------------------------------------------------------------------------

#define N_ROWS   1024
#define KDIM     49152                 // 64 * 768
#define BK_GROUP 8
#define NGROUPS  (N_ROWS / BK_GROUP)   // 128

#define BM 128
#define BN 128
#define BKC 32                         // k per stage
#define SPLITK 4
#define KSPLIT (KDIM / SPLITK)         // 12288
#define NITER  (KSPLIT / BKC)          // 384
#define NTB    (N_ROWS / BM)           // 8
#define NTILES (NTB * (NTB + 1) / 2)   // 36
#define LDA    (BKC + 8)               // smem pitch in bf16 (80B): ldmatrix conflict-free

// Scratch (device globals: allocation-free per harness rules)
__device__ __align__(128) __nv_bfloat16 g_fbf[(size_t)N_ROWS * KDIM]; // 96 MiB
__device__ float g_sq[N_ROWS];
__device__ float g_part[(size_t)NTILES * SPLITK * BM * BN];           // 9.4 MiB
__device__ float g_tileloss[NTILES][2];

// ---------------------------------------------------------------------------
// K1: fp32 -> bf16 conversion + per-row squared norm
// ---------------------------------------------------------------------------
__global__ __launch_bounds__(512) void k_convert(const float* __restrict__ x) {
    const int row = blockIdx.x;
    const float* xr = x + (size_t)row * KDIM;
    __nv_bfloat16* fr = g_fbf + (size_t)row * KDIM;

    float s = 0.0f;
    for (int i = threadIdx.x * 4; i < KDIM; i += blockDim.x * 4) {
        float4 v = *reinterpret_cast<const float4*>(xr + i);
        s += v.x * v.x + v.y * v.y + v.z * v.z + v.w * v.w;
        __nv_bfloat162 lo = __floats2bfloat162_rn(v.x, v.y);
        __nv_bfloat162 hi = __floats2bfloat162_rn(v.z, v.w);
        uint2 packed;
        packed.x = *reinterpret_cast<uint32_t*>(&lo);
        packed.y = *reinterpret_cast<uint32_t*>(&hi);
        *reinterpret_cast<uint2*>(fr + i) = packed;
    }

    __shared__ float red[16];
    int lane = threadIdx.x & 31, warp = threadIdx.x >> 5;
    #pragma unroll
    for (int o = 16; o; o >>= 1) s += __shfl_xor_sync(0xffffffffu, s, o);
    if (lane == 0) red[warp] = s;
    __syncthreads();
    if (warp == 0) {
        float v = (lane < 16) ? red[lane] : 0.0f;
        #pragma unroll
        for (int o = 8; o; o >>= 1) v += __shfl_xor_sync(0xffffffffu, v, o);
        if (lane == 0) g_sq[row] = v;
    }
}

// ---------------------------------------------------------------------------
// K2: bf16 Gram, lower-tri 128x128 tiles, split-K, cp.async double buffer
// ---------------------------------------------------------------------------
__device__ __forceinline__ uint32_t smem_u32(const void* p) {
    return (uint32_t)__cvta_generic_to_shared(p);
}

__device__ __forceinline__ void cp16(uint32_t dst, const void* src) {
    asm volatile("cp.async.cg.shared.global [%0], [%1], 16;\n" :: "r"(dst), "l"(src));
}

__global__ __launch_bounds__(256, 1) void k_gemm() {
    const int t = blockIdx.x;       // 0..35 (lower-tri tile index)
    const int split = blockIdx.y;   // 0..3

    int bi = 0;
    while ((bi + 1) * (bi + 2) / 2 <= t) bi++;
    const int bj = t - bi * (bi + 1) / 2;

    const int row0 = bi * BM;
    const int col0 = bj * BN;
    const int k_begin = split * KSPLIT;

    __shared__ __align__(16) __nv_bfloat16 As[2][BM][LDA];
    __shared__ __align__(16) __nv_bfloat16 Bs[2][BN][LDA];

    const int tid  = threadIdx.x;
    const int warp = tid >> 5;
    const int lane = tid & 31;
    const int wm = warp >> 2;           // 0..1 (64 rows)
    const int wn = warp & 3;            // 0..3 (32 cols)
    const int wrow = wm * 64;
    const int wcol = wn * 32;

    float acc[4][4][4];
    #pragma unroll
    for (int im = 0; im < 4; im++)
        #pragma unroll
        for (int in = 0; in < 4; in++)
            #pragma unroll
            for (int e = 0; e < 4; e++) acc[im][in][e] = 0.0f;

    // ldmatrix source coords
    const int a_r = lane & 15;
    const int a_c = (lane >> 4) << 3;
    const int b_r = lane & 7;
    const int b_c = (lane & 8) ? 8 : 0;

    // cp.async chunk coords: 512 chunks of 16B per 128x32 panel, 2 per thread
    const int r0 = tid >> 2;            // rows 0..63 handled by tid, +64 second pass
    const int kk0 = (tid & 3) << 3;     // 0,8,16,24

    auto load_stage = [&](int buf, int k0) {
        const __nv_bfloat16* ga = &g_fbf[(size_t)(row0 + r0) * KDIM + k0 + kk0];
        const __nv_bfloat16* gb = &g_fbf[(size_t)(col0 + r0) * KDIM + k0 + kk0];
        cp16(smem_u32(&As[buf][r0][kk0]), ga);
        cp16(smem_u32(&As[buf][r0 + 64][kk0]), ga + (size_t)64 * KDIM);
        cp16(smem_u32(&Bs[buf][r0][kk0]), gb);
        cp16(smem_u32(&Bs[buf][r0 + 64][kk0]), gb + (size_t)64 * KDIM);
        asm volatile("cp.async.commit_group;\n" ::);
    };

    load_stage(0, k_begin);

    for (int i = 0; i < NITER; i++) {
        const int buf = i & 1;
        asm volatile("cp.async.wait_group 0;\n" ::);
        __syncthreads();
        if (i + 1 < NITER) load_stage(buf ^ 1, k_begin + (i + 1) * BKC);

        #pragma unroll
        for (int kk = 0; kk < BKC; kk += 16) {
            uint32_t af[4][4];
            uint32_t bf[4][2];
            #pragma unroll
            for (int im = 0; im < 4; im++) {
                uint32_t addr = smem_u32(&As[buf][wrow + im * 16 + a_r][kk + a_c]);
                asm volatile(
                    "ldmatrix.sync.aligned.m8n8.x4.shared.b16 {%0,%1,%2,%3}, [%4];"
                    : "=r"(af[im][0]), "=r"(af[im][1]), "=r"(af[im][2]), "=r"(af[im][3])
                    : "r"(addr));
            }
            #pragma unroll
            for (int in = 0; in < 4; in++) {
                uint32_t addr = smem_u32(&Bs[buf][wcol + in * 8 + b_r][kk + b_c]);
                asm volatile(
                    "ldmatrix.sync.aligned.m8n8.x2.trans.shared.b16 {%0,%1}, [%2];"
                    : "=r"(bf[in][0]), "=r"(bf[in][1])
                    : "r"(addr));
            }
            #pragma unroll
            for (int im = 0; im < 4; im++)
                #pragma unroll
                for (int in = 0; in < 4; in++) {
                    asm volatile(
                        "mma.sync.aligned.m16n8k16.row.col.f32.bf16.bf16.f32 "
                        "{%0,%1,%2,%3}, {%4,%5,%6,%7}, {%8,%9}, {%0,%1,%2,%3};"
                        : "+f"(acc[im][in][0]), "+f"(acc[im][in][1]),
                          "+f"(acc[im][in][2]), "+f"(acc[im][in][3])
                        : "r"(af[im][0]), "r"(af[im][1]), "r"(af[im][2]), "r"(af[im][3]),
                          "r"(bf[in][0]), "r"(bf[in][1]));
                }
        }
        __syncthreads();
    }

    // epilogue: fp32 partial tile per split (deterministic reduce in K3)
    float* out = g_part + ((size_t)t * SPLITK + split) * (BM * BN);
    const int er = lane >> 2;
    const int ec = (lane & 3) << 1;
    #pragma unroll
    for (int im = 0; im < 4; im++)
        #pragma unroll
        for (int in = 0; in < 4; in++) {
            const int rg = wrow + im * 16 + er;
            const int cg = wcol + in * 8 + ec;
            *reinterpret_cast<float2*>(&out[rg * BN + cg]) =
                make_float2(acc[im][in][0], acc[im][in][1]);
            *reinterpret_cast<float2*>(&out[(rg + 8) * BN + cg]) =
                make_float2(acc[im][in][2], acc[im][in][3]);
        }
}

// ---------------------------------------------------------------------------
// K3: per-tile loss reduction (dist + masks), deterministic
// ---------------------------------------------------------------------------
__global__ __launch_bounds__(256) void k_loss() {
    const int t = blockIdx.x;
    int bi = 0;
    while ((bi + 1) * (bi + 2) / 2 <= t) bi++;
    const int bj = t - bi * (bi + 1) / 2;

    float homo = 0.0f, heter = 0.0f;
    const float* base = g_part + (size_t)t * SPLITK * (BM * BN);

    for (int e = threadIdx.x; e < BM * BN; e += blockDim.x) {
        const int rl = e >> 7;
        const int cl = e & 127;
        if (bi == bj && rl <= cl) continue;   // strict lower triangle on diagonal tiles
        float dot = 0.0f;
        #pragma unroll
        for (int s = 0; s < SPLITK; s++) dot += base[(size_t)s * (BM * BN) + e];
        const int j = bi * BM + rl;
        const int k = bj * BN + cl;
        const float dist = fmaxf(g_sq[j] + g_sq[k] - 2.0f * dot, 0.0f);
        if ((j >> 3) == (k >> 3)) homo += dist;                 // same group (size 8)
        else heter += 2.0f * fmaxf(1.0f - dist, 0.0f);          // ordered => x2
    }

    __shared__ float sh[8], se[8];
    const int lane = threadIdx.x & 31, warp = threadIdx.x >> 5;
    #pragma unroll
    for (int o = 16; o; o >>= 1) {
        homo  += __shfl_xor_sync(0xffffffffu, homo, o);
        heter += __shfl_xor_sync(0xffffffffu, heter, o);
    }
    if (lane == 0) { sh[warp] = homo; se[warp] = heter; }
    __syncthreads();
    if (warp == 0) {
        float h = (lane < 8) ? sh[lane] : 0.0f;
        float x = (lane < 8) ? se[lane] : 0.0f;
        #pragma unroll
        for (int o = 4; o; o >>= 1) {
            h += __shfl_xor_sync(0xffffffffu, h, o);
            x += __shfl_xor_sync(0xffffffffu, x, o);
        }
        if (lane == 0) { g_tileloss[t][0] = h; g_tileloss[t][1] = x; }
    }
}

// ---------------------------------------------------------------------------
// K4: final fixed-order sum + scaling
// ---------------------------------------------------------------------------
__global__ void k_final(float* __restrict__ out) {
    float h = 0.0f, e = 0.0f;
    for (int t = threadIdx.x; t < NTILES; t += 32) {
        h += g_tileloss[t][0];
        e += g_tileloss[t][1];
    }
    #pragma unroll
    for (int o = 16; o; o >>= 1) {
        h += __shfl_xor_sync(0xffffffffu, h, o);
        e += __shfl_xor_sync(0xffffffffu, e, o);
    }
    if (threadIdx.x == 0) {
        out[0] = 2.0f * h / ((float)N_ROWS * (float)(BK_GROUP - 1));
        out[1] = 2.0f * e / ((float)N_ROWS * (float)(NGROUPS - 1));
    }
}

// ---------------------------------------------------------------------------
extern "C" void kernel_launch(void* const* d_in, const int* in_sizes, int n_in,
                              void* d_out, int out_size) {
    const float* x = (const float*)d_in[0];
    float* out = (float*)d_out;

    k_convert<<<N_ROWS, 512>>>(x);
    dim3 ggrid(NTILES, SPLITK);
    k_gemm<<<ggrid, 256>>>();
    k_loss<<<NTILES, 256>>>();
    k_final<<<1, 32>>>(out);
}

// round 5
// speedup vs baseline: 1.3878x; 1.3878x over previous
#include <cuda_runtime.h>
#include <cuda_bf16.h>
#include <cstdint>

// ---------------------------------------------------------------------------
// MetricLoss: x [1024, 64, 768] fp32 -> (loss_homo_scaled, loss_heter_scaled)
//   f = x.reshape(1024, 49152)
//   dist[j,k] = max(||f_j||^2 + ||f_k||^2 - 2 f_j.f_k, 0)
//   homo  = sum over unordered same-group pairs of dist        (groups of 8)
//   heter = sum over ORDERED diff-group pairs of max(1-dist,0)
//   out0 = 2*homo / (N*(bk-1)),  out1 = 2*heter / (N*(n_groups-1))
// Strategy: bf16 Gram, lower triangle only, split-K=8, 3-stage cp.async
// pipelined mma.sync mainloop (1 barrier/iter), 2 CTAs/SM, fp32 accum,
// deterministic tile reductions.
// ---------------------------------------------------------------------------

#define N_ROWS   1024
#define KDIM     49152                 // 64 * 768
#define BK_GROUP 8
#define NGROUPS  (N_ROWS / BK_GROUP)   // 128

#define BM 128
#define BN 128
#define BKC 64                         // k per stage
#define STAGES 3
#define SPLITK 8
#define KSPLIT (KDIM / SPLITK)         // 6144
#define NITER  (KSPLIT / BKC)          // 96
#define NTB    (N_ROWS / BM)           // 8
#define NTILES (NTB * (NTB + 1) / 2)   // 36
#define LDA    (BKC + 8)               // smem pitch (144B): ldmatrix conflict-free
#define PANEL_ELEMS (BM * LDA)         // per panel per stage
#define SMEM_BYTES (STAGES * 2 * PANEL_ELEMS * 2)   // 110592

// Scratch (device globals: allocation-free per harness rules)
__device__ __align__(128) __nv_bfloat16 g_fbf[(size_t)N_ROWS * KDIM]; // 96 MiB
__device__ float g_sq[N_ROWS];
__device__ float g_part[(size_t)NTILES * SPLITK * BM * BN];           // 18.9 MiB
__device__ float g_tileloss[NTILES][2];

// ---------------------------------------------------------------------------
// K1: fp32 -> bf16 conversion + per-row squared norm
// ---------------------------------------------------------------------------
__global__ __launch_bounds__(512) void k_convert(const float* __restrict__ x) {
    const int row = blockIdx.x;
    const float* xr = x + (size_t)row * KDIM;
    __nv_bfloat16* fr = g_fbf + (size_t)row * KDIM;

    float s = 0.0f;
    for (int i = threadIdx.x * 4; i < KDIM; i += blockDim.x * 4) {
        float4 v = *reinterpret_cast<const float4*>(xr + i);
        s += v.x * v.x + v.y * v.y + v.z * v.z + v.w * v.w;
        __nv_bfloat162 lo = __floats2bfloat162_rn(v.x, v.y);
        __nv_bfloat162 hi = __floats2bfloat162_rn(v.z, v.w);
        uint2 packed;
        packed.x = *reinterpret_cast<uint32_t*>(&lo);
        packed.y = *reinterpret_cast<uint32_t*>(&hi);
        *reinterpret_cast<uint2*>(fr + i) = packed;
    }

    __shared__ float red[16];
    int lane = threadIdx.x & 31, warp = threadIdx.x >> 5;
    #pragma unroll
    for (int o = 16; o; o >>= 1) s += __shfl_xor_sync(0xffffffffu, s, o);
    if (lane == 0) red[warp] = s;
    __syncthreads();
    if (warp == 0) {
        float v = (lane < 16) ? red[lane] : 0.0f;
        #pragma unroll
        for (int o = 8; o; o >>= 1) v += __shfl_xor_sync(0xffffffffu, v, o);
        if (lane == 0) g_sq[row] = v;
    }
}

// ---------------------------------------------------------------------------
// K2: bf16 Gram, lower-tri tiles, split-K=8, 3-stage cp.async pipeline
// ---------------------------------------------------------------------------
__device__ __forceinline__ uint32_t smem_u32(const void* p) {
    return (uint32_t)__cvta_generic_to_shared(p);
}

__device__ __forceinline__ void cp16(uint32_t dst, const void* src) {
    asm volatile("cp.async.cg.shared.global [%0], [%1], 16;\n" :: "r"(dst), "l"(src));
}

__global__ __launch_bounds__(256, 2) void k_gemm() {
    extern __shared__ __align__(16) __nv_bfloat16 smem[];
    // stage s: A panel at s*2*PANEL_ELEMS, B panel at s*2*PANEL_ELEMS + PANEL_ELEMS

    const int t = blockIdx.x;       // 0..35 (lower-tri tile index)
    const int split = blockIdx.y;   // 0..7

    int bi = 0;
    while ((bi + 1) * (bi + 2) / 2 <= t) bi++;
    const int bj = t - bi * (bi + 1) / 2;

    const int row0 = bi * BM;
    const int col0 = bj * BN;
    const int k_begin = split * KSPLIT;

    const int tid  = threadIdx.x;
    const int warp = tid >> 5;
    const int lane = tid & 31;
    const int wm = warp >> 2;           // 0..1 (64 rows)
    const int wn = warp & 3;            // 0..3 (32 cols)
    const int wrow = wm * 64;
    const int wcol = wn * 32;

    float acc[4][4][4];
    #pragma unroll
    for (int im = 0; im < 4; im++)
        #pragma unroll
        for (int in = 0; in < 4; in++)
            #pragma unroll
            for (int e = 0; e < 4; e++) acc[im][in][e] = 0.0f;

    // ldmatrix source coords (validated layout)
    const int a_r = lane & 15;
    const int a_c = (lane >> 4) << 3;
    const int b_r = lane & 7;
    const int b_c = (lane & 8) ? 8 : 0;

    // cp.async coords: per panel 128 rows x 64 cols bf16 = 1024 chunks of 16B.
    // 256 threads -> 4 chunks/panel/thread: rows r0, r0+32, r0+64, r0+96.
    const int r0  = tid >> 3;           // 0..31
    const int kc  = (tid & 7) << 3;     // 0,8,...,56 (bf16 col)

    auto load_stage = [&](int s, int k0) {
        __nv_bfloat16* As = smem + (size_t)s * 2 * PANEL_ELEMS;
        __nv_bfloat16* Bs = As + PANEL_ELEMS;
        const __nv_bfloat16* ga = &g_fbf[(size_t)(row0 + r0) * KDIM + k0 + kc];
        const __nv_bfloat16* gb = &g_fbf[(size_t)(col0 + r0) * KDIM + k0 + kc];
        #pragma unroll
        for (int rb = 0; rb < 4; rb++) {
            cp16(smem_u32(&As[(r0 + rb * 32) * LDA + kc]), ga + (size_t)(rb * 32) * KDIM);
            cp16(smem_u32(&Bs[(r0 + rb * 32) * LDA + kc]), gb + (size_t)(rb * 32) * KDIM);
        }
    };

    // prologue: stages 0 and 1, one commit group per stage
    load_stage(0, k_begin);
    asm volatile("cp.async.commit_group;\n" ::);
    load_stage(1, k_begin + BKC);
    asm volatile("cp.async.commit_group;\n" ::);

    for (int i = 0; i < NITER; i++) {
        const int buf = i % STAGES;
        // stage i is group index i in commit order; committed so far = i+2;
        // allow 1 pending (stage i+1 in flight) -> stage i done.
        asm volatile("cp.async.wait_group 1;\n" ::);
        __syncthreads();   // visibility of stage i to all warps; all warps done with iter i-1

        // issue stage i+2 into buf (i+2)%3 == (i-1)%3 (computed at iter i-1, safe after sync)
        if (i + 2 < NITER) load_stage((i + 2) % STAGES, k_begin + (i + 2) * BKC);
        asm volatile("cp.async.commit_group;\n" ::);   // always commit (keeps group count aligned)

        const __nv_bfloat16* As = smem + (size_t)buf * 2 * PANEL_ELEMS;
        const __nv_bfloat16* Bs = As + PANEL_ELEMS;

        #pragma unroll
        for (int kk = 0; kk < BKC; kk += 16) {
            uint32_t af[4][4];
            uint32_t bf[4][2];
            #pragma unroll
            for (int im = 0; im < 4; im++) {
                uint32_t addr = smem_u32(&As[(wrow + im * 16 + a_r) * LDA + kk + a_c]);
                asm volatile(
                    "ldmatrix.sync.aligned.m8n8.x4.shared.b16 {%0,%1,%2,%3}, [%4];"
                    : "=r"(af[im][0]), "=r"(af[im][1]), "=r"(af[im][2]), "=r"(af[im][3])
                    : "r"(addr));
            }
            #pragma unroll
            for (int in = 0; in < 4; in++) {
                uint32_t addr = smem_u32(&Bs[(wcol + in * 8 + b_r) * LDA + kk + b_c]);
                asm volatile(
                    "ldmatrix.sync.aligned.m8n8.x2.trans.shared.b16 {%0,%1}, [%2];"
                    : "=r"(bf[in][0]), "=r"(bf[in][1])
                    : "r"(addr));
            }
            #pragma unroll
            for (int im = 0; im < 4; im++)
                #pragma unroll
                for (int in = 0; in < 4; in++) {
                    asm volatile(
                        "mma.sync.aligned.m16n8k16.row.col.f32.bf16.bf16.f32 "
                        "{%0,%1,%2,%3}, {%4,%5,%6,%7}, {%8,%9}, {%0,%1,%2,%3};"
                        : "+f"(acc[im][in][0]), "+f"(acc[im][in][1]),
                          "+f"(acc[im][in][2]), "+f"(acc[im][in][3])
                        : "r"(af[im][0]), "r"(af[im][1]), "r"(af[im][2]), "r"(af[im][3]),
                          "r"(bf[in][0]), "r"(bf[in][1]));
                }
        }
    }

    // epilogue: fp32 partial tile per split (deterministic reduce in K3)
    float* out = g_part + ((size_t)t * SPLITK + split) * (BM * BN);
    const int er = lane >> 2;
    const int ec = (lane & 3) << 1;
    #pragma unroll
    for (int im = 0; im < 4; im++)
        #pragma unroll
        for (int in = 0; in < 4; in++) {
            const int rg = wrow + im * 16 + er;
            const int cg = wcol + in * 8 + ec;
            *reinterpret_cast<float2*>(&out[rg * BN + cg]) =
                make_float2(acc[im][in][0], acc[im][in][1]);
            *reinterpret_cast<float2*>(&out[(rg + 8) * BN + cg]) =
                make_float2(acc[im][in][2], acc[im][in][3]);
        }
}

// ---------------------------------------------------------------------------
// K3: per-tile loss reduction (dist + masks), deterministic
// ---------------------------------------------------------------------------
__global__ __launch_bounds__(256) void k_loss() {
    const int t = blockIdx.x;
    int bi = 0;
    while ((bi + 1) * (bi + 2) / 2 <= t) bi++;
    const int bj = t - bi * (bi + 1) / 2;

    float homo = 0.0f, heter = 0.0f;
    const float* base = g_part + (size_t)t * SPLITK * (BM * BN);

    for (int e = threadIdx.x; e < BM * BN; e += blockDim.x) {
        const int rl = e >> 7;
        const int cl = e & 127;
        if (bi == bj && rl <= cl) continue;   // strict lower triangle on diagonal tiles
        float dot = 0.0f;
        #pragma unroll
        for (int s = 0; s < SPLITK; s++) dot += base[(size_t)s * (BM * BN) + e];
        const int j = bi * BM + rl;
        const int k = bj * BN + cl;
        const float dist = fmaxf(g_sq[j] + g_sq[k] - 2.0f * dot, 0.0f);
        if ((j >> 3) == (k >> 3)) homo += dist;                 // same group (size 8)
        else heter += 2.0f * fmaxf(1.0f - dist, 0.0f);          // ordered => x2
    }

    __shared__ float sh[8], se[8];
    const int lane = threadIdx.x & 31, warp = threadIdx.x >> 5;
    #pragma unroll
    for (int o = 16; o; o >>= 1) {
        homo  += __shfl_xor_sync(0xffffffffu, homo, o);
        heter += __shfl_xor_sync(0xffffffffu, heter, o);
    }
    if (lane == 0) { sh[warp] = homo; se[warp] = heter; }
    __syncthreads();
    if (warp == 0) {
        float h = (lane < 8) ? sh[lane] : 0.0f;
        float x = (lane < 8) ? se[lane] : 0.0f;
        #pragma unroll
        for (int o = 4; o; o >>= 1) {
            h += __shfl_xor_sync(0xffffffffu, h, o);
            x += __shfl_xor_sync(0xffffffffu, x, o);
        }
        if (lane == 0) { g_tileloss[t][0] = h; g_tileloss[t][1] = x; }
    }
}

// ---------------------------------------------------------------------------
// K4: final fixed-order sum + scaling
// ---------------------------------------------------------------------------
__global__ void k_final(float* __restrict__ out) {
    float h = 0.0f, e = 0.0f;
    for (int t = threadIdx.x; t < NTILES; t += 32) {
        h += g_tileloss[t][0];
        e += g_tileloss[t][1];
    }
    #pragma unroll
    for (int o = 16; o; o >>= 1) {
        h += __shfl_xor_sync(0xffffffffu, h, o);
        e += __shfl_xor_sync(0xffffffffu, e, o);
    }
    if (threadIdx.x == 0) {
        out[0] = 2.0f * h / ((float)N_ROWS * (float)(BK_GROUP - 1));
        out[1] = 2.0f * e / ((float)N_ROWS * (float)(NGROUPS - 1));
    }
}

// ---------------------------------------------------------------------------
extern "C" void kernel_launch(void* const* d_in, const int* in_sizes, int n_in,
                              void* d_out, int out_size) {
    const float* x = (const float*)d_in[0];
    float* out = (float*)d_out;

    cudaFuncSetAttribute(k_gemm, cudaFuncAttributeMaxDynamicSharedMemorySize, SMEM_BYTES);

    k_convert<<<N_ROWS, 512>>>(x);
    dim3 ggrid(NTILES, SPLITK);
    k_gemm<<<ggrid, 256, SMEM_BYTES>>>();
    k_loss<<<NTILES, 256>>>();
    k_final<<<1, 32>>>(out);
}

// round 7
// speedup vs baseline: 1.4539x; 1.0476x over previous
#include <cuda_runtime.h>
#include <cuda_bf16.h>
#include <cstdint>

// ---------------------------------------------------------------------------
// MetricLoss: x [1024, 64, 768] fp32 -> (loss_homo_scaled, loss_heter_scaled)
//   f = x.reshape(1024, 49152)
//   dist[j,k] = max(||f_j||^2 + ||f_k||^2 - 2 f_j.f_k, 0)
//   homo  = sum over unordered same-group pairs of dist        (groups of 8)
//   heter = sum over ORDERED diff-group pairs of max(1-dist,0)
// Strategy: bf16 Gram via mma.sync (sm_100 base target: NO tcgen05!),
// lower triangle only, split-K=8, 3-stage cp.async pipeline,
// 4 warps/CTA with 64x64 warp tiles (minimal smem-crossbar traffic),
// ldmatrix.x4 for both operands, fp32 accum, deterministic reductions.
// ---------------------------------------------------------------------------

#define N_ROWS   1024
#define KDIM     49152                 // 64 * 768
#define BK_GROUP 8
#define NGROUPS  (N_ROWS / BK_GROUP)   // 128

#define BM 128
#define BN 128
#define BKC 64                         // k per stage
#define STAGES 3
#define SPLITK 8
#define KSPLIT (KDIM / SPLITK)         // 6144
#define NITER  (KSPLIT / BKC)          // 96
#define NTB    (N_ROWS / BM)           // 8
#define NTILES (NTB * (NTB + 1) / 2)   // 36
#define LDA    (BKC + 8)               // smem pitch (144B): ldmatrix conflict-free
#define PANEL_ELEMS (BM * LDA)
#define SMEM_BYTES (STAGES * 2 * PANEL_ELEMS * 2)   // 110592

// Scratch (device globals: allocation-free per harness rules)
__device__ __align__(128) __nv_bfloat16 g_fbf[(size_t)N_ROWS * KDIM]; // 96 MiB
__device__ float g_sq[N_ROWS];
__device__ float g_part[(size_t)NTILES * SPLITK * BM * BN];
__device__ float g_tileloss[NTILES][2];

// ---------------------------------------------------------------------------
// K1: fp32 -> bf16 conversion + per-row squared norm
// ---------------------------------------------------------------------------
__global__ __launch_bounds__(512) void k_convert(const float* __restrict__ x) {
    const int row = blockIdx.x;
    const float* xr = x + (size_t)row * KDIM;
    __nv_bfloat16* fr = g_fbf + (size_t)row * KDIM;

    float s = 0.0f;
    for (int i = threadIdx.x * 4; i < KDIM; i += blockDim.x * 4) {
        float4 v = *reinterpret_cast<const float4*>(xr + i);
        s += v.x * v.x + v.y * v.y + v.z * v.z + v.w * v.w;
        __nv_bfloat162 lo = __floats2bfloat162_rn(v.x, v.y);
        __nv_bfloat162 hi = __floats2bfloat162_rn(v.z, v.w);
        uint2 packed;
        packed.x = *reinterpret_cast<uint32_t*>(&lo);
        packed.y = *reinterpret_cast<uint32_t*>(&hi);
        *reinterpret_cast<uint2*>(fr + i) = packed;
    }

    __shared__ float red[16];
    int lane = threadIdx.x & 31, warp = threadIdx.x >> 5;
    #pragma unroll
    for (int o = 16; o; o >>= 1) s += __shfl_xor_sync(0xffffffffu, s, o);
    if (lane == 0) red[warp] = s;
    __syncthreads();
    if (warp == 0) {
        float v = (lane < 16) ? red[lane] : 0.0f;
        #pragma unroll
        for (int o = 8; o; o >>= 1) v += __shfl_xor_sync(0xffffffffu, v, o);
        if (lane == 0) g_sq[row] = v;
    }
}

// ---------------------------------------------------------------------------
// K2: bf16 Gram, lower-tri tiles, split-K=8, 3-stage cp.async, 4 warps
// ---------------------------------------------------------------------------
__device__ __forceinline__ uint32_t smem_u32(const void* p) {
    return (uint32_t)__cvta_generic_to_shared(p);
}
__device__ __forceinline__ void cp16(uint32_t dst, const void* src) {
    asm volatile("cp.async.cg.shared.global [%0], [%1], 16;\n" :: "r"(dst), "l"(src));
}

__global__ __launch_bounds__(128, 2) void k_gemm() {
    extern __shared__ __align__(16) __nv_bfloat16 smem[];
    // stage s: A panel at s*2*PANEL_ELEMS, B panel at +PANEL_ELEMS

    const int t = blockIdx.x;       // 0..35 (lower-tri tile index)
    const int split = blockIdx.y;   // 0..7

    int bi = 0;
    while ((bi + 1) * (bi + 2) / 2 <= t) bi++;
    const int bj = t - bi * (bi + 1) / 2;

    const int row0 = bi * BM;
    const int col0 = bj * BN;
    const int k_begin = split * KSPLIT;

    const int tid  = threadIdx.x;
    const int warp = tid >> 5;
    const int lane = tid & 31;
    const int wm = warp >> 1;           // 0..1 -> 64 rows each
    const int wn = warp & 1;            // 0..1 -> 64 cols each
    const int wrow = wm * 64;
    const int wcol = wn * 64;

    // acc[im][in][4]: im 0..3 (16-row steps), in 0..7 (8-col steps)
    float acc[4][8][4];
    #pragma unroll
    for (int im = 0; im < 4; im++)
        #pragma unroll
        for (int in = 0; in < 8; in++)
            #pragma unroll
            for (int e = 0; e < 4; e++) acc[im][in][e] = 0.0f;

    // ldmatrix coords
    const int a_r = lane & 15;              // A: row within 16
    const int a_c = (lane >> 4) << 3;       // A: k offset 0/8
    const int b_r = (lane & 7) + ((lane & 16) ? 8 : 0);  // B: n within 16 (2 n8 blocks)
    const int b_c = (lane & 8) ? 8 : 0;                  // B: k offset 0/8

    // cp.async: per stage 2048 chunks of 16B (A:1024, B:1024); 16 per thread.
    const int r0 = tid >> 3;            // 0..15
    const int kc = (tid & 7) << 3;      // 0,8,...,56 (bf16 col)

    auto load_stage = [&](int s, int k0) {
        __nv_bfloat16* As = smem + (size_t)s * 2 * PANEL_ELEMS;
        __nv_bfloat16* Bs = As + PANEL_ELEMS;
        const __nv_bfloat16* ga = &g_fbf[(size_t)(row0 + r0) * KDIM + k0 + kc];
        const __nv_bfloat16* gb = &g_fbf[(size_t)(col0 + r0) * KDIM + k0 + kc];
        #pragma unroll
        for (int rb = 0; rb < 8; rb++) {
            cp16(smem_u32(&As[(r0 + rb * 16) * LDA + kc]), ga + (size_t)(rb * 16) * KDIM);
            cp16(smem_u32(&Bs[(r0 + rb * 16) * LDA + kc]), gb + (size_t)(rb * 16) * KDIM);
        }
    };

    load_stage(0, k_begin);
    asm volatile("cp.async.commit_group;\n" ::);
    load_stage(1, k_begin + BKC);
    asm volatile("cp.async.commit_group;\n" ::);

    for (int i = 0; i < NITER; i++) {
        const int buf = i % STAGES;
        asm volatile("cp.async.wait_group 1;\n" ::);
        __syncthreads();

        if (i + 2 < NITER) load_stage((i + 2) % STAGES, k_begin + (i + 2) * BKC);
        asm volatile("cp.async.commit_group;\n" ::);

        const __nv_bfloat16* As = smem + (size_t)buf * 2 * PANEL_ELEMS;
        const __nv_bfloat16* Bs = As + PANEL_ELEMS;

        #pragma unroll
        for (int kk = 0; kk < BKC; kk += 16) {
            uint32_t af[4][4];
            uint32_t bf[4][4];
            #pragma unroll
            for (int im = 0; im < 4; im++) {
                uint32_t addr = smem_u32(&As[(wrow + im * 16 + a_r) * LDA + kk + a_c]);
                asm volatile(
                    "ldmatrix.sync.aligned.m8n8.x4.shared.b16 {%0,%1,%2,%3}, [%4];"
                    : "=r"(af[im][0]), "=r"(af[im][1]), "=r"(af[im][2]), "=r"(af[im][3])
                    : "r"(addr));
            }
            #pragma unroll
            for (int inp = 0; inp < 4; inp++) {
                uint32_t addr = smem_u32(&Bs[(wcol + inp * 16 + b_r) * LDA + kk + b_c]);
                asm volatile(
                    "ldmatrix.sync.aligned.m8n8.x4.trans.shared.b16 {%0,%1,%2,%3}, [%4];"
                    : "=r"(bf[inp][0]), "=r"(bf[inp][1]), "=r"(bf[inp][2]), "=r"(bf[inp][3])
                    : "r"(addr));
            }
            #pragma unroll
            for (int im = 0; im < 4; im++)
                #pragma unroll
                for (int in = 0; in < 8; in++) {
                    const int inp  = in >> 1;
                    const int pair = (in & 1) << 1;
                    asm volatile(
                        "mma.sync.aligned.m16n8k16.row.col.f32.bf16.bf16.f32 "
                        "{%0,%1,%2,%3}, {%4,%5,%6,%7}, {%8,%9}, {%0,%1,%2,%3};"
                        : "+f"(acc[im][in][0]), "+f"(acc[im][in][1]),
                          "+f"(acc[im][in][2]), "+f"(acc[im][in][3])
                        : "r"(af[im][0]), "r"(af[im][1]), "r"(af[im][2]), "r"(af[im][3]),
                          "r"(bf[inp][pair]), "r"(bf[inp][pair + 1]));
                }
        }
    }

    // epilogue: fp32 partial tile per split (row-major, deterministic reduce in K3)
    float* out = g_part + ((size_t)t * SPLITK + split) * (BM * BN);
    const int er = lane >> 2;
    const int ec = (lane & 3) << 1;
    #pragma unroll
    for (int im = 0; im < 4; im++)
        #pragma unroll
        for (int in = 0; in < 8; in++) {
            const int rg = wrow + im * 16 + er;
            const int cg = wcol + in * 8 + ec;
            *reinterpret_cast<float2*>(&out[rg * BN + cg]) =
                make_float2(acc[im][in][0], acc[im][in][1]);
            *reinterpret_cast<float2*>(&out[(rg + 8) * BN + cg]) =
                make_float2(acc[im][in][2], acc[im][in][3]);
        }
}

// ---------------------------------------------------------------------------
// K3: per-tile loss reduction (dist + masks), deterministic
// ---------------------------------------------------------------------------
__global__ __launch_bounds__(256) void k_loss() {
    const int t = blockIdx.x;
    int bi = 0;
    while ((bi + 1) * (bi + 2) / 2 <= t) bi++;
    const int bj = t - bi * (bi + 1) / 2;

    float homo = 0.0f, heter = 0.0f;
    const float* base = g_part + (size_t)t * SPLITK * (BM * BN);

    for (int e = threadIdx.x; e < BM * BN; e += blockDim.x) {
        const int rl = e >> 7;
        const int cl = e & 127;
        if (bi == bj && rl <= cl) continue;   // strict lower triangle on diagonal tiles
        float dot = 0.0f;
        #pragma unroll
        for (int s = 0; s < SPLITK; s++) dot += base[(size_t)s * (BM * BN) + e];
        const int j = bi * BM + rl;
        const int k = bj * BN + cl;
        const float dist = fmaxf(g_sq[j] + g_sq[k] - 2.0f * dot, 0.0f);
        if ((j >> 3) == (k >> 3)) homo += dist;                 // same group (size 8)
        else heter += 2.0f * fmaxf(1.0f - dist, 0.0f);          // ordered => x2
    }

    __shared__ float sh[8], se[8];
    const int lane = threadIdx.x & 31, warp = threadIdx.x >> 5;
    #pragma unroll
    for (int o = 16; o; o >>= 1) {
        homo  += __shfl_xor_sync(0xffffffffu, homo, o);
        heter += __shfl_xor_sync(0xffffffffu, heter, o);
    }
    if (lane == 0) { sh[warp] = homo; se[warp] = heter; }
    __syncthreads();
    if (warp == 0) {
        float h = (lane < 8) ? sh[lane] : 0.0f;
        float x = (lane < 8) ? se[lane] : 0.0f;
        #pragma unroll
        for (int o = 4; o; o >>= 1) {
            h += __shfl_xor_sync(0xffffffffu, h, o);
            x += __shfl_xor_sync(0xffffffffu, x, o);
        }
        if (lane == 0) { g_tileloss[t][0] = h; g_tileloss[t][1] = x; }
    }
}

// ---------------------------------------------------------------------------
// K4: final fixed-order sum + scaling
// ---------------------------------------------------------------------------
__global__ void k_final(float* __restrict__ out) {
    float h = 0.0f, e = 0.0f;
    for (int t = threadIdx.x; t < NTILES; t += 32) {
        h += g_tileloss[t][0];
        e += g_tileloss[t][1];
    }
    #pragma unroll
    for (int o = 16; o; o >>= 1) {
        h += __shfl_xor_sync(0xffffffffu, h, o);
        e += __shfl_xor_sync(0xffffffffu, e, o);
    }
    if (threadIdx.x == 0) {
        out[0] = 2.0f * h / ((float)N_ROWS * (float)(BK_GROUP - 1));
        out[1] = 2.0f * e / ((float)N_ROWS * (float)(NGROUPS - 1));
    }
}

// ---------------------------------------------------------------------------
extern "C" void kernel_launch(void* const* d_in, const int* in_sizes, int n_in,
                              void* d_out, int out_size) {
    const float* x = (const float*)d_in[0];
    float* out = (float*)d_out;

    cudaFuncSetAttribute(k_gemm, cudaFuncAttributeMaxDynamicSharedMemorySize, SMEM_BYTES);

    k_convert<<<N_ROWS, 512>>>(x);
    dim3 ggrid(NTILES, SPLITK);
    k_gemm<<<ggrid, 128, SMEM_BYTES>>>();
    k_loss<<<NTILES, 256>>>();
    k_final<<<1, 32>>>(out);
}